// round 5
// baseline (speedup 1.0000x reference)
#include <cuda_runtime.h>
#include <math.h>

typedef unsigned long long u64;

// ---------------- f32x2 packed helpers (sm_103a) ----------------
__device__ __forceinline__ u64 pk2(float lo, float hi) {
    u64 r; asm("mov.b64 %0, {%1, %2};" : "=l"(r) : "f"(lo), "f"(hi)); return r;
}
__device__ __forceinline__ u64 dup2(float v) { return pk2(v, v); }
__device__ __forceinline__ void upk2(u64 p, float& lo, float& hi) {
    asm("mov.b64 {%0, %1}, %2;" : "=f"(lo), "=f"(hi) : "l"(p));
}
__device__ __forceinline__ void fma2(u64& d, u64 a, u64 b) {
    asm("fma.rn.f32x2 %0, %1, %2, %0;" : "+l"(d) : "l"(a), "l"(b));
}

// ---------------- problem constants ----------------
#define BB   64
#define CIN  64
#define T0   4096
#define HH   64
#define H    128
#define T1   2048
#define T2   1024
#define RH   64
#define DD   64
#define KCB  512
#define NN   (BB * T2)

// ---------------- scratch ----------------
__device__ float g_h1[(size_t)BB * HH * T1];
__device__ float g_h2[(size_t)BB * H  * T2];
__device__ float g_h3[(size_t)BB * H  * T2];
__device__ float g_WcT[H * DD];     // fused (wpq @ w_out), [ch][dq]
__device__ float g_bc[DD];
__device__ float g_cnorm[KCB];
__device__ int   g_hist[KCB];
__device__ float g_losssum;

// ---------------- precompute (parallel): WcT, bc, cnorm, zero scalars ----------------
__global__ void precompute_k(const float* __restrict__ wpq, const float* __restrict__ w_out,
                             const float* __restrict__ b_out, const float* __restrict__ bpq,
                             const float* __restrict__ cb)
{
    const int bid = blockIdx.x, tid = threadIdx.x;
    if (bid < 64) {                      // one block per dq: WcT column
        __shared__ float wrow[64];
        if (tid < 64) wrow[tid] = wpq[bid * DD + tid];
        __syncthreads();
        float s = 0.f;                   // tid = ch (0..127)
        #pragma unroll
        for (int d = 0; d < DD; d++) s = fmaf(wrow[d], w_out[d * H + tid], s);
        g_WcT[tid * DD + bid] = s;
    } else if (bid == 64) {
        if (tid < DD) {
            float s = bpq[tid];
            #pragma unroll
            for (int d = 0; d < DD; d++) s = fmaf(wpq[tid * DD + d], b_out[d], s);
            g_bc[tid] = s;
        }
        if (tid == 0) g_losssum = 0.f;
    } else {                              // bid == 65: cnorm + hist
        for (int k = tid; k < KCB; k += 128) {
            float s = 0.f;
            #pragma unroll
            for (int d = 0; d < DD; d++) { float c = cb[k * DD + d]; s = fmaf(c, c, s); }
            g_cnorm[k] = s;
            g_hist[k] = 0;
        }
    }
}

// ---------------- K=4 stride=2 pad=1 conv, bias + relu, f32x2 ----------------
__global__ void __launch_bounds__(128) convS2_k(
    const float* __restrict__ in, const float* __restrict__ w,
    const float* __restrict__ bias, float* __restrict__ out,
    int Cin, int Tin, int Cout, int Tout)
{
    __shared__ __align__(16) float sx[16 * 258];
    __shared__ __align__(16) float swt[16 * 65];

    const int tid = threadIdx.x;
    const int cs  = tid & 7;            // pair of co: co0+cs*2 (+0,+1)
    const int ts  = tid >> 3;           // 8 t each
    const int t0  = blockIdx.x * 128;
    const int co0 = blockIdx.y * 16;
    const int b   = blockIdx.z;

    u64 acc2[8];
    {
        u64 bv = pk2(bias[co0 + cs * 2], bias[co0 + cs * 2 + 1]);
        #pragma unroll
        for (int j = 0; j < 8; j++) acc2[j] = bv;
    }

    for (int cc = 0; cc < Cin; cc += 16) {
        for (int idx = tid; idx < 16 * 258; idx += 128) {
            int ci = idx / 258, p = idx - ci * 258;
            int g = 2 * t0 - 1 + p;
            sx[idx] = (g >= 0 && g < Tin) ? in[((size_t)b * Cin + cc + ci) * Tin + g] : 0.f;
        }
        for (int idx = tid; idx < 16 * 64; idx += 128) {
            int co = idx >> 6, r = idx & 63;
            swt[co * 65 + r] = w[(size_t)(co0 + co) * Cin * 4 + cc * 4 + r];
        }
        __syncthreads();

        #pragma unroll 2
        for (int ci = 0; ci < 16; ci++) {
            u64 xd[18];
            #pragma unroll
            for (int p = 0; p < 18; p++) xd[p] = dup2(sx[ci * 258 + ts * 16 + p]);
            u64 wp[4];
            const float* wr = &swt[(cs * 2) * 65 + ci * 4];
            #pragma unroll
            for (int k = 0; k < 4; k++) wp[k] = pk2(wr[k], wr[65 + k]);
            #pragma unroll
            for (int j = 0; j < 8; j++)
                #pragma unroll
                for (int k = 0; k < 4; k++)
                    fma2(acc2[j], xd[2 * j + k], wp[k]);
        }
        __syncthreads();
    }

    float a0[8], a1[8];
    #pragma unroll
    for (int j = 0; j < 8; j++) { upk2(acc2[j], a0[j], a1[j]); }
    {
        float4* op = (float4*)(out + ((size_t)b * Cout + co0 + cs * 2) * Tout + t0 + ts * 8);
        op[0] = make_float4(fmaxf(a0[0],0.f), fmaxf(a0[1],0.f), fmaxf(a0[2],0.f), fmaxf(a0[3],0.f));
        op[1] = make_float4(fmaxf(a0[4],0.f), fmaxf(a0[5],0.f), fmaxf(a0[6],0.f), fmaxf(a0[7],0.f));
    }
    {
        float4* op = (float4*)(out + ((size_t)b * Cout + co0 + cs * 2 + 1) * Tout + t0 + ts * 8);
        op[0] = make_float4(fmaxf(a1[0],0.f), fmaxf(a1[1],0.f), fmaxf(a1[2],0.f), fmaxf(a1[3],0.f));
        op[1] = make_float4(fmaxf(a1[4],0.f), fmaxf(a1[5],0.f), fmaxf(a1[6],0.f), fmaxf(a1[7],0.f));
    }
}

// ---------------- K=3 stride=1 pad=1 conv, bias, no relu (conv3), f32x2 ----------------
__global__ void __launch_bounds__(128) convS1_k(
    const float* __restrict__ in, const float* __restrict__ w,
    const float* __restrict__ bias, float* __restrict__ out,
    int Cin, int Cout)
{
    __shared__ __align__(16) float sx[32 * 130];
    __shared__ __align__(16) float swt[16 * 97];

    const int tid = threadIdx.x;
    const int cs  = tid & 7;
    const int ts  = tid >> 3;
    const int t0  = blockIdx.x * 128;
    const int co0 = blockIdx.y * 16;
    const int b   = blockIdx.z;

    u64 acc2[8];
    {
        u64 bv = pk2(bias[co0 + cs * 2], bias[co0 + cs * 2 + 1]);
        #pragma unroll
        for (int j = 0; j < 8; j++) acc2[j] = bv;
    }

    for (int cc = 0; cc < Cin; cc += 32) {
        for (int idx = tid; idx < 32 * 130; idx += 128) {
            int ci = idx / 130, p = idx - ci * 130;
            int g = t0 - 1 + p;
            sx[idx] = (g >= 0 && g < T2) ? in[((size_t)b * Cin + cc + ci) * T2 + g] : 0.f;
        }
        for (int idx = tid; idx < 16 * 96; idx += 128) {
            int co = idx / 96, r = idx - co * 96;
            swt[co * 97 + r] = w[(size_t)(co0 + co) * Cin * 3 + cc * 3 + r];
        }
        __syncthreads();

        #pragma unroll 2
        for (int ci = 0; ci < 32; ci++) {
            u64 xd[10];
            #pragma unroll
            for (int p = 0; p < 10; p++) xd[p] = dup2(sx[ci * 130 + ts * 8 + p]);
            u64 wp[3];
            const float* wr = &swt[(cs * 2) * 97 + ci * 3];
            #pragma unroll
            for (int k = 0; k < 3; k++) wp[k] = pk2(wr[k], wr[97 + k]);
            #pragma unroll
            for (int j = 0; j < 8; j++)
                #pragma unroll
                for (int k = 0; k < 3; k++)
                    fma2(acc2[j], xd[j + k], wp[k]);
        }
        __syncthreads();
    }

    float a0[8], a1[8];
    #pragma unroll
    for (int j = 0; j < 8; j++) { upk2(acc2[j], a0[j], a1[j]); }
    {
        float4* op = (float4*)(out + ((size_t)b * Cout + co0 + cs * 2) * T2 + t0 + ts * 8);
        op[0] = make_float4(a0[0], a0[1], a0[2], a0[3]);
        op[1] = make_float4(a0[4], a0[5], a0[6], a0[7]);
    }
    {
        float4* op = (float4*)(out + ((size_t)b * Cout + co0 + cs * 2 + 1) * T2 + t0 + ts * 8);
        op[0] = make_float4(a1[0], a1[1], a1[2], a1[3]);
        op[1] = make_float4(a1[4], a1[5], a1[6], a1[7]);
    }
}

// ---------------- fused residual block (512 threads, f32x2) ----------------
// sh holds relu(h); residual re-read from global in epilogue.
#define RB_SH  (128 * 130)
#define RB_STA (64 * 130)
#define RB_SW  (64 * 385)
__global__ void __launch_bounds__(512) resblock_k(
    const float* __restrict__ in, const float* __restrict__ wa,
    const float* __restrict__ wb, float* __restrict__ out)
{
    extern __shared__ float s[];
    float* sh  = s;              // relu'd h [128][130]
    float* sta = s + RB_SH;      // mid tile [64][130]
    float* sw  = sta + RB_STA;   // wa [64][385], later wb [64][130]

    const int tid = threadIdx.x;
    const int t0  = blockIdx.x * 128;
    const int b   = blockIdx.z;

    for (int idx = tid; idx < RB_SH; idx += 512) {
        int ci = idx / 130, p = idx - ci * 130;
        int g = t0 - 1 + p;
        sh[idx] = (g >= 0 && g < T2) ? fmaxf(in[((size_t)b * H + ci) * T2 + g], 0.f) : 0.f;
    }
    for (int idx = tid; idx < 64 * 384; idx += 512) {
        int m = idx / 384, r = idx - m * 384;
        sw[m * 385 + r] = wa[idx];
    }
    __syncthreads();

    // phase B: mid = relu(conv3(sh)), thread = mids {mslot, mslot+32} x 8 t
    {
        const int mslot = tid & 31;
        const int tslot = tid >> 5;
        u64 acc2[8];
        #pragma unroll
        for (int j = 0; j < 8; j++) acc2[j] = 0ull;

        #pragma unroll 2
        for (int ci = 0; ci < H; ci++) {
            u64 xd[10];
            #pragma unroll
            for (int p = 0; p < 10; p++) xd[p] = dup2(sh[ci * 130 + tslot * 8 + p]);
            u64 wp[3];
            const float* wr = &sw[mslot * 385 + ci * 3];
            #pragma unroll
            for (int k = 0; k < 3; k++) wp[k] = pk2(wr[k], wr[32 * 385 + k]);
            #pragma unroll
            for (int j = 0; j < 8; j++)
                #pragma unroll
                for (int k = 0; k < 3; k++)
                    fma2(acc2[j], xd[j + k], wp[k]);
        }
        #pragma unroll
        for (int j = 0; j < 8; j++) {
            float lo, hi; upk2(acc2[j], lo, hi);
            sta[mslot * 130 + tslot * 8 + j]        = fmaxf(lo, 0.f);
            sta[(mslot + 32) * 130 + tslot * 8 + j] = fmaxf(hi, 0.f);
        }
    }
    __syncthreads();

    // reload sw region with wb transposed: swb[mid][co]
    for (int idx = tid; idx < H * RH; idx += 512) {
        int co = idx >> 6, mid = idx & 63;
        sw[mid * 130 + co] = wb[idx];
    }
    __syncthreads();

    // phase C: out = in + wb @ mid; thread = co {coslot+32c} x 8 t
    {
        const int coslot = tid & 31;
        const int tslot  = tid >> 5;
        u64 acc2[4][4];
        #pragma unroll
        for (int c = 0; c < 4; c++)
            #pragma unroll
            for (int jp = 0; jp < 4; jp++) acc2[c][jp] = 0ull;

        #pragma unroll 2
        for (int mid = 0; mid < RH; mid++) {
            u64 xv2[4];
            #pragma unroll
            for (int jp = 0; jp < 4; jp++)
                xv2[jp] = *(const u64*)&sta[mid * 130 + tslot * 8 + 2 * jp];
            #pragma unroll
            for (int c = 0; c < 4; c++) {
                u64 wv = dup2(sw[mid * 130 + coslot + 32 * c]);
                #pragma unroll
                for (int jp = 0; jp < 4; jp++) fma2(acc2[c][jp], xv2[jp], wv);
            }
        }

        #pragma unroll
        for (int c = 0; c < 4; c++) {
            int co = coslot + 32 * c;
            const float4* ip = (const float4*)(in + ((size_t)b * H + co) * T2 + t0 + tslot * 8);
            float4 r0 = ip[0], r1 = ip[1];
            float a[8];
            #pragma unroll
            for (int jp = 0; jp < 4; jp++) upk2(acc2[c][jp], a[2 * jp], a[2 * jp + 1]);
            float4* op = (float4*)(out + ((size_t)b * H + co) * T2 + t0 + tslot * 8);
            op[0] = make_float4(r0.x + a[0], r0.y + a[1], r0.z + a[2], r0.w + a[3]);
            op[1] = make_float4(r1.x + a[4], r1.y + a[5], r1.z + a[6], r1.w + a[7]);
        }
    }
}

// ---------------- fused relu + (wpq o w_out) + transpose -> z_e, f32x2 ----------------
#define ZSH (128 * 128)
#define ZSW (128 * 65)
__global__ void __launch_bounds__(128) zfused_k(const float* __restrict__ h, float* __restrict__ ze)
{
    extern __shared__ float s[];
    float* sh = s;          // relu'd [128 ch][128 t]
    float* sw = s + ZSH;    // WcT [128 ch][65]

    const int tid = threadIdx.x;
    const int t0  = blockIdx.x * 128;
    const int b   = blockIdx.z;

    for (int idx = tid; idx < 128 * 128; idx += 128) {
        int ci = idx >> 7, t = idx & 127;
        sh[idx] = fmaxf(h[((size_t)b * H + ci) * T2 + t0 + t], 0.f);
    }
    for (int idx = tid; idx < H * DD; idx += 128) {
        int ch = idx >> 6, dq = idx & 63;
        sw[ch * 65 + dq] = g_WcT[idx];
    }
    __syncthreads();

    const int dqslot = tid & 7;
    const int tslot  = tid >> 3;
    const int dq0 = dqslot * 8;

    u64 acc2[8][4];
    #pragma unroll
    for (int c = 0; c < 8; c++) {
        u64 bv = dup2(g_bc[dq0 + c]);
        #pragma unroll
        for (int jp = 0; jp < 4; jp++) acc2[c][jp] = bv;
    }

    #pragma unroll 2
    for (int ch = 0; ch < H; ch++) {
        u64 xv2[4];
        #pragma unroll
        for (int jp = 0; jp < 4; jp++)
            xv2[jp] = *(const u64*)&sh[ch * 128 + tslot * 8 + 2 * jp];
        #pragma unroll
        for (int c = 0; c < 8; c++) {
            u64 wv = dup2(sw[ch * 65 + dq0 + c]);
            #pragma unroll
            for (int jp = 0; jp < 4; jp++) fma2(acc2[c][jp], xv2[jp], wv);
        }
    }

    float av[8][8];
    #pragma unroll
    for (int c = 0; c < 8; c++)
        #pragma unroll
        for (int jp = 0; jp < 4; jp++)
            upk2(acc2[c][jp], av[c][2 * jp], av[c][2 * jp + 1]);

    #pragma unroll
    for (int j = 0; j < 8; j++) {
        size_t n = (size_t)b * T2 + t0 + tslot * 8 + j;
        float2* op = (float2*)(ze + n * DD + dq0);   // 8B-aligned region
        op[0] = make_float2(av[0][j], av[1][j]);
        op[1] = make_float2(av[2][j], av[3][j]);
        op[2] = make_float2(av[4][j], av[5][j]);
        op[3] = make_float2(av[6][j], av[7][j]);
    }
}

// ---------------- VQ distance-GEMM, f32x2, dup codebook; writes full one-hot rows ----------------
#define VQ_SZ (64 * 130)               // szeT floats
#define VQ_CD (64 * 66)                // scbD u64 count
__global__ void __launch_bounds__(256) vqgemm_k(
    const float* __restrict__ ze, const float* __restrict__ cb,
    float* __restrict__ zq, float* __restrict__ enc, float* __restrict__ idxout)
{
    extern __shared__ float s[];
    float* szeT = s;                         // [64 d][130]
    u64*   scbD = (u64*)(s + VQ_SZ);         // [64 d][66] duplicated pairs
    float* scn  = (float*)(scbD + VQ_CD);    // [512]
    int*   sbk  = (int*)(scn + KCB);         // [128]

    const int tid = threadIdx.x;
    const int n0  = blockIdx.x * 128;

    for (int idx = tid; idx < 128 * DD; idx += 256) {
        int n = idx >> 6, d = idx & 63;
        szeT[d * 130 + n] = ze[(size_t)(n0 + n) * DD + d];
    }
    for (int k = tid; k < KCB; k += 256) scn[k] = g_cnorm[k];
    __syncthreads();

    const int nslot = tid >> 3;    // n = nslot*4 + i
    const int kslot = tid & 7;     // k = kc + kslot + 8j

    float best[4] = {3.4e38f, 3.4e38f, 3.4e38f, 3.4e38f};
    int   bk[4]   = {0, 0, 0, 0};

    for (int kc = 0; kc < KCB; kc += 64) {
        for (int idx = tid; idx < 64 * 64; idx += 256) {
            int k = idx >> 6, d = idx & 63;
            scbD[d * 66 + k] = dup2(cb[(size_t)(kc + k) * DD + d]);
        }
        __syncthreads();

        u64 acc2[2][8];
        #pragma unroll
        for (int p = 0; p < 2; p++)
            #pragma unroll
            for (int j = 0; j < 8; j++) acc2[p][j] = 0ull;

        #pragma unroll 2
        for (int d = 0; d < DD; d++) {
            u64 f0 = *(const u64*)&szeT[d * 130 + nslot * 4];
            u64 f1 = *(const u64*)&szeT[d * 130 + nslot * 4 + 2];
            #pragma unroll
            for (int j = 0; j < 8; j++) {
                u64 c2 = scbD[d * 66 + kslot + 8 * j];
                fma2(acc2[0][j], f0, c2);
                fma2(acc2[1][j], f1, c2);
            }
        }

        #pragma unroll
        for (int p = 0; p < 2; p++)
            #pragma unroll
            for (int j = 0; j < 8; j++) {
                float dlo, dhi; upk2(acc2[p][j], dlo, dhi);
                int kg = kc + kslot + 8 * j;
                float cn = scn[kg];
                float dist0 = cn - 2.f * dlo;
                float dist1 = cn - 2.f * dhi;
                int i0 = 2 * p, i1 = 2 * p + 1;
                if (dist0 < best[i0]) { best[i0] = dist0; bk[i0] = kg; }
                if (dist1 < best[i1]) { best[i1] = dist1; bk[i1] = kg; }
            }
        __syncthreads();
    }

    // reduce over 8 kslot lanes (width 8), tie-break to smaller index
    #pragma unroll
    for (int off = 4; off > 0; off >>= 1) {
        #pragma unroll
        for (int i = 0; i < 4; i++) {
            float ob = __shfl_down_sync(0xffffffffu, best[i], off, 8);
            int   ok = __shfl_down_sync(0xffffffffu, bk[i],   off, 8);
            if (ob < best[i] || (ob == best[i] && ok < bk[i])) { best[i] = ob; bk[i] = ok; }
        }
    }
    if (kslot == 0)
        #pragma unroll
        for (int i = 0; i < 4; i++) sbk[nslot * 4 + i] = bk[i];
    __syncthreads();

    // z_q gather + loss partial
    float part = 0.f;
    for (int idx = tid; idx < 128 * DD; idx += 256) {
        int nl = idx >> 6, d = idx & 63;
        int kk = sbk[nl];
        float c = cb[(size_t)kk * DD + d];
        float f = szeT[d * 130 + nl];
        zq[(size_t)(n0 + nl) * DD + d] = c;
        float df = c - f;
        part = fmaf(df, df, part);
    }

    // one-hot rows: zero-fill (fused, replaces separate kernel) then set 1.0
    const float2 z2 = make_float2(0.f, 0.f);
    for (int r = 0; r < 128; r++) {
        float2* rp = (float2*)(enc + (size_t)(n0 + r) * KCB);
        rp[tid] = z2;
    }
    __syncthreads();
    if (tid < 128) {
        int kk = sbk[tid];
        idxout[n0 + tid] = (float)kk;
        enc[(size_t)(n0 + tid) * KCB + kk] = 1.f;
        atomicAdd(&g_hist[kk], 1);
    }

    #pragma unroll
    for (int o = 16; o > 0; o >>= 1) part += __shfl_down_sync(0xffffffffu, part, o);
    __shared__ float wsum[8];
    if ((tid & 31) == 0) wsum[tid >> 5] = part;
    __syncthreads();
    if (tid < 8) {
        float v = wsum[tid];
        #pragma unroll
        for (int o = 4; o > 0; o >>= 1) v += __shfl_down_sync(0xffu, v, o);
        if (tid == 0) atomicAdd(&g_losssum, v);
    }
}

// ---------------- finalize scalars ----------------
__global__ void fin_k(float* __restrict__ loss_out, float* __restrict__ perp_out)
{
    __shared__ float red[512];
    const int k = threadIdx.x;
    float p = (float)g_hist[k] * (1.0f / (float)NN);
    red[k] = p * logf(p + 1e-10f);
    __syncthreads();
    for (int s2 = 256; s2 > 0; s2 >>= 1) {
        if (k < s2) red[k] += red[k + s2];
        __syncthreads();
    }
    if (k == 0) {
        perp_out[0] = expf(-red[0]);
        loss_out[0] = 1.25f * g_losssum / (float)((size_t)NN * DD);
    }
}

// ---------------- launcher ----------------
extern "C" void kernel_launch(void* const* d_in, const int* in_sizes, int n_in,
                              void* d_out, int out_size)
{
    const float* x     = (const float*)d_in[0];
    const float* w1    = (const float*)d_in[1];
    const float* b1    = (const float*)d_in[2];
    const float* w2    = (const float*)d_in[3];
    const float* b2    = (const float*)d_in[4];
    const float* w3    = (const float*)d_in[5];
    const float* b3    = (const float*)d_in[6];
    const float* r0w1  = (const float*)d_in[7];
    const float* r0w2  = (const float*)d_in[8];
    const float* r1w1  = (const float*)d_in[9];
    const float* r1w2  = (const float*)d_in[10];
    const float* w_out = (const float*)d_in[11];
    const float* b_out = (const float*)d_in[12];
    const float* wpq   = (const float*)d_in[13];
    const float* bpq   = (const float*)d_in[14];
    const float* cb    = (const float*)d_in[15];

    float* outp = (float*)d_out;
    const size_t NZ = (size_t)NN * DD;
    float* o_loss = outp;
    float* o_zq   = outp + 1;
    float* o_perp = outp + 1 + NZ;
    float* o_ze   = outp + 2 + NZ;
    float* o_enc  = outp + 2 + 2 * NZ;
    float* o_idx  = outp + 2 + 2 * NZ + (size_t)NN * KCB;

    static int attr_done = 0;
    const int res_smem = (RB_SH + RB_STA + RB_SW) * 4;        // 198,400
    const int z_smem   = (ZSH + ZSW) * 4;                     // 98,816
    const int vq_smem  = VQ_SZ * 4 + VQ_CD * 8 + KCB * 4 + 128 * 4;  // 69,632
    if (!attr_done) {
        cudaFuncSetAttribute(resblock_k, cudaFuncAttributeMaxDynamicSharedMemorySize, res_smem);
        cudaFuncSetAttribute(zfused_k,   cudaFuncAttributeMaxDynamicSharedMemorySize, z_smem);
        cudaFuncSetAttribute(vqgemm_k,   cudaFuncAttributeMaxDynamicSharedMemorySize, vq_smem);
        attr_done = 1;
    }

    precompute_k<<<66, 128>>>(wpq, w_out, b_out, bpq, cb);

    convS2_k<<<dim3(T1 / 128, HH / 16, BB), 128>>>(x,    w1, b1, g_h1, CIN, T0, HH, T1);
    convS2_k<<<dim3(T2 / 128, H  / 16, BB), 128>>>(g_h1, w2, b2, g_h2, HH,  T1, H,  T2);
    convS1_k<<<dim3(T2 / 128, H  / 16, BB), 128>>>(g_h2, w3, b3, g_h3, H, H);

    resblock_k<<<dim3(T2 / 128, 1, BB), 512, res_smem>>>(g_h3, r0w1, r0w2, g_h2);
    resblock_k<<<dim3(T2 / 128, 1, BB), 512, res_smem>>>(g_h2, r1w1, r1w2, g_h3);

    zfused_k<<<dim3(T2 / 128, 1, BB), 128, z_smem>>>(g_h3, o_ze);

    vqgemm_k<<<NN / 128, 256, vq_smem>>>(o_ze, cb, o_zq, o_enc, o_idx);

    fin_k<<<1, 512>>>(o_loss, o_perp);
}

// round 6
// speedup vs baseline: 1.6794x; 1.6794x over previous
#include <cuda_runtime.h>
#include <math.h>

#define BB   64
#define CIN  64
#define T0   4096
#define HH   64
#define H    128
#define T1   2048
#define T2   1024
#define RH   64
#define DD   64
#define KCB  512
#define NN   (BB * T2)

__device__ float g_h1[(size_t)BB * HH * T1];
__device__ float g_h2[(size_t)BB * H  * T2];
__device__ float g_h3[(size_t)BB * H  * T2];
__device__ float g_WcT[H * DD];
__device__ float g_bc[DD];
__device__ float g_cnorm[KCB];
__device__ int   g_hist[KCB];
__device__ float g_losssum;

// ---------------- precompute ----------------
__global__ void precompute_k(const float* __restrict__ wpq, const float* __restrict__ w_out,
                             const float* __restrict__ b_out, const float* __restrict__ bpq,
                             const float* __restrict__ cb)
{
    const int bid = blockIdx.x, tid = threadIdx.x;
    if (bid < 64) {
        __shared__ float wrow[64];
        if (tid < 64) wrow[tid] = wpq[bid * DD + tid];
        __syncthreads();
        float s = 0.f;
        #pragma unroll
        for (int d = 0; d < DD; d++) s = fmaf(wrow[d], w_out[d * H + tid], s);
        g_WcT[tid * DD + bid] = s;
    } else if (bid == 64) {
        if (tid < DD) {
            float s = bpq[tid];
            #pragma unroll
            for (int d = 0; d < DD; d++) s = fmaf(wpq[tid * DD + d], b_out[d], s);
            g_bc[tid] = s;
        }
        if (tid == 0) g_losssum = 0.f;
    } else {
        for (int k = tid; k < KCB; k += 128) {
            float s = 0.f;
            #pragma unroll
            for (int d = 0; d < DD; d++) { float c = cb[k * DD + d]; s = fmaf(c, c, s); }
            g_cnorm[k] = s;
            g_hist[k] = 0;
        }
    }
}

// ---------------- K=4 S=2 pad=1 conv + bias + relu; 256 thr, thread = 4co x 8t ----------------
__global__ void __launch_bounds__(256) convS2_k(
    const float* __restrict__ in, const float* __restrict__ w,
    const float* __restrict__ bias, float* __restrict__ out,
    int Cin, int Tin, int Cout, int Tout)
{
    __shared__ __align__(16) float sx[16 * 264];   // [ci][p], p <-> 2*t0-1+p, span 258
    __shared__ __align__(16) float sw[16 * 4 * 64]; // [ci][k][co]

    const int tid = threadIdx.x;
    const int tslot = tid & 15;        // 8 t each
    const int cslot = tid >> 4;        // 4 co each
    const int t0  = blockIdx.x * 128;
    const int co0 = blockIdx.y * 64;
    const int b   = blockIdx.z;

    float acc[4][8];
    #pragma unroll
    for (int c = 0; c < 4; c++) {
        float bv = bias[co0 + cslot * 4 + c];
        #pragma unroll
        for (int j = 0; j < 8; j++) acc[c][j] = bv;
    }

    for (int cc = 0; cc < Cin; cc += 16) {
        for (int idx = tid; idx < 16 * 258; idx += 256) {
            int ci = idx / 258, p = idx - ci * 258;
            int g = 2 * t0 - 1 + p;
            sx[ci * 264 + p] = (g >= 0 && g < Tin) ? in[((size_t)b * Cin + cc + ci) * Tin + g] : 0.f;
        }
        for (int idx = tid; idx < 16 * 4 * 64; idx += 256) {
            int co = idx & 63, r = idx >> 6;       // r = ci*4+k
            int ci = r >> 2, k = r & 3;
            sw[idx] = w[(size_t)((co0 + co) * Cin + cc + ci) * 4 + k];
        }
        __syncthreads();

        #pragma unroll 2
        for (int ci = 0; ci < 16; ci++) {
            float x[18];
            const float* xr = &sx[ci * 264 + tslot * 16];
            #pragma unroll
            for (int q = 0; q < 4; q++) {
                float4 v = *(const float4*)(xr + 4 * q);
                x[4*q] = v.x; x[4*q+1] = v.y; x[4*q+2] = v.z; x[4*q+3] = v.w;
            }
            { float2 v = *(const float2*)(xr + 16); x[16] = v.x; x[17] = v.y; }
            float wv[4][4];
            #pragma unroll
            for (int k = 0; k < 4; k++) {
                float4 v = *(const float4*)&sw[(ci * 4 + k) * 64 + cslot * 4];
                wv[k][0] = v.x; wv[k][1] = v.y; wv[k][2] = v.z; wv[k][3] = v.w;
            }
            #pragma unroll
            for (int c = 0; c < 4; c++)
                #pragma unroll
                for (int j = 0; j < 8; j++)
                    #pragma unroll
                    for (int k = 0; k < 4; k++)
                        acc[c][j] = fmaf(x[2 * j + k], wv[k][c], acc[c][j]);
        }
        __syncthreads();
    }

    #pragma unroll
    for (int c = 0; c < 4; c++) {
        float4* op = (float4*)(out + ((size_t)b * Cout + co0 + cslot * 4 + c) * Tout + t0 + tslot * 8);
        op[0] = make_float4(fmaxf(acc[c][0],0.f), fmaxf(acc[c][1],0.f), fmaxf(acc[c][2],0.f), fmaxf(acc[c][3],0.f));
        op[1] = make_float4(fmaxf(acc[c][4],0.f), fmaxf(acc[c][5],0.f), fmaxf(acc[c][6],0.f), fmaxf(acc[c][7],0.f));
    }
}

// ---------------- K=3 S=1 pad=1 conv + bias (no relu); 256 thr, 4co x 8t ----------------
__global__ void __launch_bounds__(256) convS1_k(
    const float* __restrict__ in, const float* __restrict__ w,
    const float* __restrict__ bias, float* __restrict__ out,
    int Cin, int Cout)
{
    __shared__ __align__(16) float sx[16 * 136];    // span 130
    __shared__ __align__(16) float sw[16 * 3 * 64]; // [ci][k][co]

    const int tid = threadIdx.x;
    const int tslot = tid & 15;
    const int cslot = tid >> 4;
    const int t0  = blockIdx.x * 128;
    const int co0 = blockIdx.y * 64;
    const int b   = blockIdx.z;

    float acc[4][8];
    #pragma unroll
    for (int c = 0; c < 4; c++) {
        float bv = bias[co0 + cslot * 4 + c];
        #pragma unroll
        for (int j = 0; j < 8; j++) acc[c][j] = bv;
    }

    for (int cc = 0; cc < Cin; cc += 16) {
        for (int idx = tid; idx < 16 * 130; idx += 256) {
            int ci = idx / 130, p = idx - ci * 130;
            int g = t0 - 1 + p;
            sx[ci * 136 + p] = (g >= 0 && g < T2) ? in[((size_t)b * Cin + cc + ci) * T2 + g] : 0.f;
        }
        for (int idx = tid; idx < 16 * 3 * 64; idx += 256) {
            int ci = idx / 192, rem = idx - ci * 192;
            int k = rem >> 6, co = rem & 63;
            sw[(ci * 3 + k) * 64 + co] = w[(size_t)((co0 + co) * Cin + cc + ci) * 3 + k];
        }
        __syncthreads();

        #pragma unroll 2
        for (int ci = 0; ci < 16; ci++) {
            float x[10];
            const float* xr = &sx[ci * 136 + tslot * 8];
            { float4 v = *(const float4*)(xr);     x[0]=v.x; x[1]=v.y; x[2]=v.z; x[3]=v.w; }
            { float4 v = *(const float4*)(xr + 4); x[4]=v.x; x[5]=v.y; x[6]=v.z; x[7]=v.w; }
            { float2 v = *(const float2*)(xr + 8); x[8]=v.x; x[9]=v.y; }
            float wv[3][4];
            #pragma unroll
            for (int k = 0; k < 3; k++) {
                float4 v = *(const float4*)&sw[(ci * 3 + k) * 64 + cslot * 4];
                wv[k][0] = v.x; wv[k][1] = v.y; wv[k][2] = v.z; wv[k][3] = v.w;
            }
            #pragma unroll
            for (int c = 0; c < 4; c++)
                #pragma unroll
                for (int j = 0; j < 8; j++)
                    #pragma unroll
                    for (int k = 0; k < 3; k++)
                        acc[c][j] = fmaf(x[j + k], wv[k][c], acc[c][j]);
        }
        __syncthreads();
    }

    #pragma unroll
    for (int c = 0; c < 4; c++) {
        float4* op = (float4*)(out + ((size_t)b * Cout + co0 + cslot * 4 + c) * T2 + t0 + tslot * 8);
        op[0] = make_float4(acc[c][0], acc[c][1], acc[c][2], acc[c][3]);
        op[1] = make_float4(acc[c][4], acc[c][5], acc[c][6], acc[c][7]);
    }
}

// ---------------- fused residual block; 512 thr ----------------
#define RB_SH  (128 * 136)
#define RB_STA (64 * 136)
#define RB_SW  (64 * 132)   // >= 16*3*64
__global__ void __launch_bounds__(512) resblock_k(
    const float* __restrict__ in, const float* __restrict__ wa,
    const float* __restrict__ wb, float* __restrict__ out)
{
    extern __shared__ float s[];
    float* sh  = s;              // relu(h) [128 ci][136], span 130
    float* sta = s + RB_SH;      // mid [64][136], span 128
    float* sw  = sta + RB_STA;   // wa chunk [16ci][3][64mid]; later wb [mid][132co]

    const int tid = threadIdx.x;
    const int t0  = blockIdx.x * 128;
    const int b   = blockIdx.z;
    const int tslot = tid & 15;

    for (int idx = tid; idx < 128 * 130; idx += 512) {
        int ci = idx / 130, p = idx - ci * 130;
        int g = t0 - 1 + p;
        sh[ci * 136 + p] = (g >= 0 && g < T2) ? fmaxf(in[((size_t)b * H + ci) * T2 + g], 0.f) : 0.f;
    }

    // phase B: mid = relu(conv3(sh)); thread = 2 mid x 8 t
    {
        const int mslot = tid >> 4;   // 0..31, mid = mslot*2 + c
        float acc[2][8];
        #pragma unroll
        for (int c = 0; c < 2; c++)
            #pragma unroll
            for (int j = 0; j < 8; j++) acc[c][j] = 0.f;

        for (int cc = 0; cc < H; cc += 16) {
            __syncthreads();
            for (int idx = tid; idx < 16 * 3 * 64; idx += 512) {
                int mid = idx & 63, r = idx >> 6;  // r = ci*3+k
                int ci = r / 3, k = r - ci * 3;
                sw[idx] = wa[((size_t)mid * H + cc + ci) * 3 + k];
            }
            __syncthreads();

            #pragma unroll 2
            for (int ci = 0; ci < 16; ci++) {
                float x[10];
                const float* xr = &sh[(cc + ci) * 136 + tslot * 8];
                { float4 v = *(const float4*)(xr);     x[0]=v.x; x[1]=v.y; x[2]=v.z; x[3]=v.w; }
                { float4 v = *(const float4*)(xr + 4); x[4]=v.x; x[5]=v.y; x[6]=v.z; x[7]=v.w; }
                { float2 v = *(const float2*)(xr + 8); x[8]=v.x; x[9]=v.y; }
                float wv[3][2];
                #pragma unroll
                for (int k = 0; k < 3; k++) {
                    float2 v = *(const float2*)&sw[(ci * 3 + k) * 64 + mslot * 2];
                    wv[k][0] = v.x; wv[k][1] = v.y;
                }
                #pragma unroll
                for (int c = 0; c < 2; c++)
                    #pragma unroll
                    for (int j = 0; j < 8; j++)
                        #pragma unroll
                        for (int k = 0; k < 3; k++)
                            acc[c][j] = fmaf(x[j + k], wv[k][c], acc[c][j]);
            }
        }
        __syncthreads();
        #pragma unroll
        for (int c = 0; c < 2; c++)
            #pragma unroll
            for (int jp = 0; jp < 4; jp++)
                *(float2*)&sta[(mslot * 2 + c) * 136 + tslot * 8 + 2 * jp] =
                    make_float2(fmaxf(acc[c][2*jp], 0.f), fmaxf(acc[c][2*jp+1], 0.f));
    }
    __syncthreads();

    // wb -> sw transposed [mid][132 pitch co]
    for (int idx = tid; idx < H * RH; idx += 512) {
        int co = idx >> 6, mid = idx & 63;
        sw[mid * 132 + co] = wb[idx];
    }
    __syncthreads();

    // phase C: out = in + wb @ mid; thread = 4 co x 8 t
    {
        const int cslot = tid >> 4;   // 0..31, co = cslot*4 + c
        float acc[4][8];
        #pragma unroll
        for (int c = 0; c < 4; c++)
            #pragma unroll
            for (int j = 0; j < 8; j++) acc[c][j] = 0.f;

        #pragma unroll 2
        for (int mid = 0; mid < RH; mid++) {
            float x[8];
            const float* xr = &sta[mid * 136 + tslot * 8];
            { float4 v = *(const float4*)(xr);     x[0]=v.x; x[1]=v.y; x[2]=v.z; x[3]=v.w; }
            { float4 v = *(const float4*)(xr + 4); x[4]=v.x; x[5]=v.y; x[6]=v.z; x[7]=v.w; }
            float4 wv = *(const float4*)&sw[mid * 132 + cslot * 4];
            float wc[4] = {wv.x, wv.y, wv.z, wv.w};
            #pragma unroll
            for (int c = 0; c < 4; c++)
                #pragma unroll
                for (int j = 0; j < 8; j++)
                    acc[c][j] = fmaf(x[j], wc[c], acc[c][j]);
        }

        #pragma unroll
        for (int c = 0; c < 4; c++) {
            int co = cslot * 4 + c;
            const float4* ip = (const float4*)(in + ((size_t)b * H + co) * T2 + t0 + tslot * 8);
            float4 r0 = ip[0], r1 = ip[1];
            float4* op = (float4*)(out + ((size_t)b * H + co) * T2 + t0 + tslot * 8);
            op[0] = make_float4(r0.x + acc[c][0], r0.y + acc[c][1], r0.z + acc[c][2], r0.w + acc[c][3]);
            op[1] = make_float4(r1.x + acc[c][4], r1.y + acc[c][5], r1.z + acc[c][6], r1.w + acc[c][7]);
        }
    }
}

// ---------------- fused relu + Wc + transpose -> z_e; 256 thr, 4dq x 8t ----------------
#define Z_SH (128 * 136)
#define Z_SW (128 * 64)
__global__ void __launch_bounds__(256) zfused_k(const float* __restrict__ h, float* __restrict__ ze)
{
    extern __shared__ float s[];
    float* sh = s;          // relu'd [128 ch][136], 128 used
    float* sw = s + Z_SH;   // WcT [128 ch][64 dq]

    const int tid = threadIdx.x;
    const int tslot = tid & 15;
    const int cslot = tid >> 4;   // dq = cslot*4 + c
    const int t0  = blockIdx.x * 128;
    const int b   = blockIdx.z;

    for (int idx = tid; idx < 128 * 128; idx += 256) {
        int ci = idx >> 7, t = idx & 127;
        sh[ci * 136 + t] = fmaxf(h[((size_t)b * H + ci) * T2 + t0 + t], 0.f);
    }
    for (int i = tid; i < (H * DD) / 4; i += 256)
        ((float4*)sw)[i] = ((const float4*)g_WcT)[i];
    __syncthreads();

    float acc[4][8];
    #pragma unroll
    for (int c = 0; c < 4; c++) {
        float bv = g_bc[cslot * 4 + c];
        #pragma unroll
        for (int j = 0; j < 8; j++) acc[c][j] = bv;
    }

    #pragma unroll 2
    for (int ch = 0; ch < H; ch++) {
        float x[8];
        const float* xr = &sh[ch * 136 + tslot * 8];
        { float4 v = *(const float4*)(xr);     x[0]=v.x; x[1]=v.y; x[2]=v.z; x[3]=v.w; }
        { float4 v = *(const float4*)(xr + 4); x[4]=v.x; x[5]=v.y; x[6]=v.z; x[7]=v.w; }
        float4 wv = *(const float4*)&sw[ch * 64 + cslot * 4];
        float wc[4] = {wv.x, wv.y, wv.z, wv.w};
        #pragma unroll
        for (int c = 0; c < 4; c++)
            #pragma unroll
            for (int j = 0; j < 8; j++)
                acc[c][j] = fmaf(x[j], wc[c], acc[c][j]);
    }

    #pragma unroll
    for (int j = 0; j < 8; j++) {
        size_t n = (size_t)b * T2 + t0 + tslot * 8 + j;
        float2* op = (float2*)(ze + n * DD + cslot * 4);   // 8B-aligned region
        op[0] = make_float2(acc[0][j], acc[1][j]);
        op[1] = make_float2(acc[2][j], acc[3][j]);
    }
}

// ---------------- VQ distance-GEMM; 256 thr, 8n x 8k, 128n x 512k per block ----------------
#define VQ_SZ (64 * 136)
#define VQ_SC (64 * 136)
__global__ void __launch_bounds__(256) vqgemm_k(
    const float* __restrict__ ze, const float* __restrict__ cb,
    float* __restrict__ zq, float* __restrict__ enc, float* __restrict__ idxout)
{
    extern __shared__ float s[];
    float* szeT = s;                 // [d64][136], 128 n used
    float* scb  = s + VQ_SZ;         // [d64][136], 128 k-chunk used
    float* scn  = scb + VQ_SC;       // [512]
    int*   sbk  = (int*)(scn + KCB); // [128]

    const int tid = threadIdx.x;
    const int n0  = blockIdx.x * 128;
    const int nslot = tid >> 4;   // 0..15, n = nslot*8 + i
    const int kslot = tid & 15;   // k = kc + kslot*8 + j

    for (int idx = tid; idx < 128 * DD; idx += 256) {
        int n = idx >> 6, d = idx & 63;
        szeT[d * 136 + n] = ze[(size_t)(n0 + n) * DD + d];
    }
    for (int k = tid; k < KCB; k += 256) scn[k] = g_cnorm[k];
    __syncthreads();

    float best[8];
    int   bk[8];
    #pragma unroll
    for (int i = 0; i < 8; i++) { best[i] = 3.4e38f; bk[i] = 0; }

    for (int kc = 0; kc < KCB; kc += 128) {
        for (int idx = tid; idx < 128 * DD; idx += 256) {
            int kk = idx >> 6, d = idx & 63;
            scb[d * 136 + kk] = cb[(size_t)(kc + kk) * DD + d];
        }
        __syncthreads();

        float acc[8][8];
        #pragma unroll
        for (int i = 0; i < 8; i++)
            #pragma unroll
            for (int j = 0; j < 8; j++) acc[i][j] = 0.f;

        #pragma unroll 2
        for (int d = 0; d < DD; d++) {
            float fz[8], fc[8];
            const float* zr = &szeT[d * 136 + nslot * 8];
            { float4 v = *(const float4*)(zr);     fz[0]=v.x; fz[1]=v.y; fz[2]=v.z; fz[3]=v.w; }
            { float4 v = *(const float4*)(zr + 4); fz[4]=v.x; fz[5]=v.y; fz[6]=v.z; fz[7]=v.w; }
            const float* cr = &scb[d * 136 + kslot * 8];
            { float4 v = *(const float4*)(cr);     fc[0]=v.x; fc[1]=v.y; fc[2]=v.z; fc[3]=v.w; }
            { float4 v = *(const float4*)(cr + 4); fc[4]=v.x; fc[5]=v.y; fc[6]=v.z; fc[7]=v.w; }
            #pragma unroll
            for (int i = 0; i < 8; i++)
                #pragma unroll
                for (int j = 0; j < 8; j++)
                    acc[i][j] = fmaf(fz[i], fc[j], acc[i][j]);
        }

        #pragma unroll
        for (int j = 0; j < 8; j++) {
            int kg = kc + kslot * 8 + j;
            float cn = scn[kg];
            #pragma unroll
            for (int i = 0; i < 8; i++) {
                float dist = cn - 2.f * acc[i][j];
                if (dist < best[i]) { best[i] = dist; bk[i] = kg; }
            }
        }
        __syncthreads();
    }

    // reduce over 16 kslot lanes (same nslot = 16 consecutive lanes), tie -> smaller k
    #pragma unroll
    for (int off = 8; off > 0; off >>= 1) {
        #pragma unroll
        for (int i = 0; i < 8; i++) {
            float ob = __shfl_down_sync(0xffffffffu, best[i], off, 16);
            int   ok = __shfl_down_sync(0xffffffffu, bk[i],   off, 16);
            if (ob < best[i] || (ob == best[i] && ok < bk[i])) { best[i] = ob; bk[i] = ok; }
        }
    }
    if (kslot == 0)
        #pragma unroll
        for (int i = 0; i < 8; i++) sbk[nslot * 8 + i] = bk[i];
    __syncthreads();

    // z_q gather + loss partial
    float part = 0.f;
    for (int idx = tid; idx < 128 * DD; idx += 256) {
        int nl = idx >> 6, d = idx & 63;
        int kk = sbk[nl];
        float c = cb[(size_t)kk * DD + d];
        float f = szeT[d * 136 + nl];
        zq[(size_t)(n0 + nl) * DD + d] = c;
        float df = c - f;
        part = fmaf(df, df, part);
    }

    // one-hot rows: zero-fill then set 1.0
    const float2 z2 = make_float2(0.f, 0.f);
    for (int r = 0; r < 128; r++) {
        float2* rp = (float2*)(enc + (size_t)(n0 + r) * KCB);
        rp[tid] = z2;
    }
    __syncthreads();
    if (tid < 128) {
        int kk = sbk[tid];
        idxout[n0 + tid] = (float)kk;
        enc[(size_t)(n0 + tid) * KCB + kk] = 1.f;
        atomicAdd(&g_hist[kk], 1);
    }

    #pragma unroll
    for (int o = 16; o > 0; o >>= 1) part += __shfl_down_sync(0xffffffffu, part, o);
    __shared__ float wsum[8];
    if ((tid & 31) == 0) wsum[tid >> 5] = part;
    __syncthreads();
    if (tid < 8) {
        float v = wsum[tid];
        #pragma unroll
        for (int o = 4; o > 0; o >>= 1) v += __shfl_down_sync(0xffu, v, o);
        if (tid == 0) atomicAdd(&g_losssum, v);
    }
}

// ---------------- finalize ----------------
__global__ void fin_k(float* __restrict__ loss_out, float* __restrict__ perp_out)
{
    __shared__ float red[512];
    const int k = threadIdx.x;
    float p = (float)g_hist[k] * (1.0f / (float)NN);
    red[k] = p * logf(p + 1e-10f);
    __syncthreads();
    for (int s2 = 256; s2 > 0; s2 >>= 1) {
        if (k < s2) red[k] += red[k + s2];
        __syncthreads();
    }
    if (k == 0) {
        perp_out[0] = expf(-red[0]);
        loss_out[0] = 1.25f * g_losssum / (float)((size_t)NN * DD);
    }
}

// ---------------- launcher ----------------
extern "C" void kernel_launch(void* const* d_in, const int* in_sizes, int n_in,
                              void* d_out, int out_size)
{
    const float* x     = (const float*)d_in[0];
    const float* w1    = (const float*)d_in[1];
    const float* b1    = (const float*)d_in[2];
    const float* w2    = (const float*)d_in[3];
    const float* b2    = (const float*)d_in[4];
    const float* w3    = (const float*)d_in[5];
    const float* b3    = (const float*)d_in[6];
    const float* r0w1  = (const float*)d_in[7];
    const float* r0w2  = (const float*)d_in[8];
    const float* r1w1  = (const float*)d_in[9];
    const float* r1w2  = (const float*)d_in[10];
    const float* w_out = (const float*)d_in[11];
    const float* b_out = (const float*)d_in[12];
    const float* wpq   = (const float*)d_in[13];
    const float* bpq   = (const float*)d_in[14];
    const float* cb    = (const float*)d_in[15];

    float* outp = (float*)d_out;
    const size_t NZ = (size_t)NN * DD;
    float* o_loss = outp;
    float* o_zq   = outp + 1;
    float* o_perp = outp + 1 + NZ;
    float* o_ze   = outp + 2 + NZ;
    float* o_enc  = outp + 2 + 2 * NZ;
    float* o_idx  = outp + 2 + 2 * NZ + (size_t)NN * KCB;

    static int attr_done = 0;
    const int res_smem = (RB_SH + RB_STA + RB_SW) * 4;   // 138,240 B
    const int z_smem   = (Z_SH + Z_SW) * 4;              // 102,400 B
    const int vq_smem  = (VQ_SZ + VQ_SC + KCB) * 4 + 128 * 4;  // 72,192 B
    if (!attr_done) {
        cudaFuncSetAttribute(resblock_k, cudaFuncAttributeMaxDynamicSharedMemorySize, res_smem);
        cudaFuncSetAttribute(zfused_k,   cudaFuncAttributeMaxDynamicSharedMemorySize, z_smem);
        cudaFuncSetAttribute(vqgemm_k,   cudaFuncAttributeMaxDynamicSharedMemorySize, vq_smem);
        attr_done = 1;
    }

    precompute_k<<<66, 128>>>(wpq, w_out, b_out, bpq, cb);

    convS2_k<<<dim3(T1 / 128, 1, BB), 256>>>(x,    w1, b1, g_h1, CIN, T0, HH, T1);
    convS2_k<<<dim3(T2 / 128, 2, BB), 256>>>(g_h1, w2, b2, g_h2, HH,  T1, H,  T2);
    convS1_k<<<dim3(T2 / 128, 2, BB), 256>>>(g_h2, w3, b3, g_h3, H, H);

    resblock_k<<<dim3(T2 / 128, 1, BB), 512, res_smem>>>(g_h3, r0w1, r0w2, g_h2);
    resblock_k<<<dim3(T2 / 128, 1, BB), 512, res_smem>>>(g_h2, r1w1, r1w2, g_h3);

    zfused_k<<<dim3(T2 / 128, 1, BB), 256, z_smem>>>(g_h3, o_ze);

    vqgemm_k<<<NN / 128, 256, vq_smem>>>(o_ze, cb, o_zq, o_enc, o_idx);

    fin_k<<<1, 512>>>(o_loss, o_perp);
}